// round 5
// baseline (speedup 1.0000x reference)
#include <cuda_runtime.h>
#include <cuda_bf16.h>

// VGAE encoder, pull-based + aggregation/GEMM commutation:
//   A_hat (X W) = (A_hat X) W, so each layer = [warp gather-aggregate over CSR,
//   then 32x32 GEMV in-register via warp shuffles]. The mu/logvar heads share
//   one aggregation. 3 fused kernels total; no scatter atomics, no standalone GEMMs.

#define N_MAX 131072
#define E_MAX 2097152

// Scratch (device globals; no allocations allowed)
__device__ int   g_is64;
__device__ int   g_alloc;            // CSR region allocator
__device__ int   g_cnt[N_MAX];       // in-degree (excluding self-loop)
__device__ int   g_rowstart[N_MAX];
__device__ int   g_cur[N_MAX];       // permutation cursor
__device__ float g_dis[N_MAX];       // deg^-1/2 (deg includes self-loop)
__device__ int2  g_adj[E_MAX];       // CSR payload: (src, __float_as_int(norm))
__device__ float g_bufA[(size_t)N_MAX * 32];
__device__ float g_bufB[(size_t)N_MAX * 32];

// ---------------------------------------------------------------------------
// Edge dtype detection (parallel): if edge_index is int64 (values < N ~ 1e5),
// every odd int32 word (high half) is 0. If int32, odd words are random src
// indices and are essentially never all zero across 512 samples.
// ---------------------------------------------------------------------------

__global__ __launch_bounds__(512) void k_detect(const int* __restrict__ ei32, int E) {
    int n_check = 512 < E ? 512 : E;
    int t = threadIdx.x;
    int nz = (t < n_check && ei32[2 * t + 1] != 0) ? 1 : 0;
    int any = __syncthreads_or(nz);
    if (t == 0) {
        g_is64 = !any;
        g_alloc = 0;
    }
}

__global__ void k_zero_cnt(int n) {
    int i = blockIdx.x * blockDim.x + threadIdx.x;
    if (i < n) g_cnt[i] = 0;
}

// Count in-degrees (reads edge list directly; no staging arrays)
__global__ void k_count(const void* __restrict__ eiv, int E) {
    int e = blockIdx.x * blockDim.x + threadIdx.x;
    if (e >= E) return;
    int d;
    if (g_is64) d = (int)((const long long*)eiv)[(size_t)E + e];
    else        d = ((const int*)eiv)[(size_t)E + e];
    atomicAdd(&g_cnt[d], 1);
}

// Atomic CSR region allocation: each node grabs a contiguous [rs, rs+cnt)
// slice of g_adj. Segment ordering across nodes is arbitrary — irrelevant
// for the warp-per-node gather, which streams its own segment.
__global__ void k_rowalloc(int n) {
    int i = blockIdx.x * blockDim.x + threadIdx.x;
    if (i >= n) return;
    int c = g_cnt[i];
    int rs = atomicAdd(&g_alloc, c);
    g_rowstart[i] = rs;
    g_cur[i] = rs;
    g_dis[i] = rsqrtf((float)(c + 1));  // +1 self-loop
}

__global__ void k_permute(const void* __restrict__ eiv, int E) {
    int e = blockIdx.x * blockDim.x + threadIdx.x;
    if (e >= E) return;
    int s, d;
    if (g_is64) {
        const long long* ei = (const long long*)eiv;
        s = (int)ei[e];
        d = (int)ei[(size_t)E + e];
    } else {
        const int* ei = (const int*)eiv;
        s = ei[e];
        d = ei[(size_t)E + e];
    }
    int pos = atomicAdd(&g_cur[d], 1);
    int2 ev;
    ev.x = s;
    ev.y = __float_as_int(g_dis[s] * g_dis[d]);
    g_adj[pos] = ev;
}

// ---------------------------------------------------------------------------
// Fused layer: one warp per node, lane = channel.
//   t[lane]  = dis_i^2 * r(h[i,lane]) + sum_j norm_j * r(h[src_j,lane])
//   out[i,lane] = sum_k t[k] * W[k,lane] + b[lane]      (shuffle GEMV)
// r() = relu if RELU.
// ---------------------------------------------------------------------------

template <int RELU>
__global__ __launch_bounds__(256) void k_layer(
    const float* __restrict__ h, const float* __restrict__ W,
    const float* __restrict__ b, float* __restrict__ out, int n)
{
    __shared__ float sW[1024];  // W[k][j] at sW[k*32+j]
    ((float4*)sW)[threadIdx.x] = ((const float4*)W)[threadIdx.x];
    __syncthreads();

    int warp = (blockIdx.x * blockDim.x + threadIdx.x) >> 5;
    int lane = threadIdx.x & 31;
    if (warp >= n) return;

    int rs = g_rowstart[warp];
    int cnt = g_cnt[warp];
    float dis = g_dis[warp];

    size_t self = (size_t)warp * 32 + lane;
    float hv = h[self];
    if (RELU) hv = fmaxf(hv, 0.0f);
    float acc = dis * dis * hv;

    int j = rs, end = rs + cnt;
    for (; j + 4 <= end; j += 4) {
        int2 e0 = g_adj[j + 0];
        int2 e1 = g_adj[j + 1];
        int2 e2 = g_adj[j + 2];
        int2 e3 = g_adj[j + 3];
        float v0 = h[(size_t)e0.x * 32 + lane];
        float v1 = h[(size_t)e1.x * 32 + lane];
        float v2 = h[(size_t)e2.x * 32 + lane];
        float v3 = h[(size_t)e3.x * 32 + lane];
        if (RELU) {
            v0 = fmaxf(v0, 0.0f); v1 = fmaxf(v1, 0.0f);
            v2 = fmaxf(v2, 0.0f); v3 = fmaxf(v3, 0.0f);
        }
        acc += __int_as_float(e0.y) * v0;
        acc += __int_as_float(e1.y) * v1;
        acc += __int_as_float(e2.y) * v2;
        acc += __int_as_float(e3.y) * v3;
    }
    for (; j < end; j++) {
        int2 ev = g_adj[j];
        float v = h[(size_t)ev.x * 32 + lane];
        if (RELU) v = fmaxf(v, 0.0f);
        acc += __int_as_float(ev.y) * v;
    }

    // GEMV: out[lane] = sum_k t[k] * W[k][lane] + b[lane]
    float o = b[lane];
#pragma unroll
    for (int k = 0; k < 32; k++) {
        float tk = __shfl_sync(0xFFFFFFFFu, acc, k);
        o += tk * sW[k * 32 + lane];
    }
    out[self] = o;
}

// Fused dual head: one aggregation, two GEMVs (mu and logvar).
__global__ __launch_bounds__(256) void k_layer2(
    const float* __restrict__ h,
    const float* __restrict__ Wa, const float* __restrict__ Wb,
    const float* __restrict__ ba, const float* __restrict__ bb,
    float* __restrict__ oa, float* __restrict__ ob, int n)
{
    __shared__ float sWa[1024];
    __shared__ float sWb[1024];
    ((float4*)sWa)[threadIdx.x] = ((const float4*)Wa)[threadIdx.x];
    ((float4*)sWb)[threadIdx.x] = ((const float4*)Wb)[threadIdx.x];
    __syncthreads();

    int warp = (blockIdx.x * blockDim.x + threadIdx.x) >> 5;
    int lane = threadIdx.x & 31;
    if (warp >= n) return;

    int rs = g_rowstart[warp];
    int cnt = g_cnt[warp];
    float dis = g_dis[warp];

    size_t self = (size_t)warp * 32 + lane;
    float acc = dis * dis * fmaxf(h[self], 0.0f);

    int j = rs, end = rs + cnt;
    for (; j + 4 <= end; j += 4) {
        int2 e0 = g_adj[j + 0];
        int2 e1 = g_adj[j + 1];
        int2 e2 = g_adj[j + 2];
        int2 e3 = g_adj[j + 3];
        float v0 = fmaxf(h[(size_t)e0.x * 32 + lane], 0.0f);
        float v1 = fmaxf(h[(size_t)e1.x * 32 + lane], 0.0f);
        float v2 = fmaxf(h[(size_t)e2.x * 32 + lane], 0.0f);
        float v3 = fmaxf(h[(size_t)e3.x * 32 + lane], 0.0f);
        acc += __int_as_float(e0.y) * v0;
        acc += __int_as_float(e1.y) * v1;
        acc += __int_as_float(e2.y) * v2;
        acc += __int_as_float(e3.y) * v3;
    }
    for (; j < end; j++) {
        int2 ev = g_adj[j];
        acc += __int_as_float(ev.y) * fmaxf(h[(size_t)ev.x * 32 + lane], 0.0f);
    }

    float omu = ba[lane];
    float olv = bb[lane];
#pragma unroll
    for (int k = 0; k < 32; k++) {
        float tk = __shfl_sync(0xFFFFFFFFu, acc, k);
        omu += tk * sWa[k * 32 + lane];
        olv += tk * sWb[k * 32 + lane];
    }
    oa[self] = omu;
    ob[self] = olv;
}

// ---------------------------------------------------------------------------
// Launch
// ---------------------------------------------------------------------------

static inline int cdiv(long long a, int b) { return (int)((a + b - 1) / b); }

extern "C" void kernel_launch(void* const* d_in, const int* in_sizes, int n_in,
                              void* d_out, int out_size)
{
    const float* x   = (const float*)d_in[0];
    const void*  ei  = d_in[1];
    const float* W1  = (const float*)d_in[2];
    const float* b1  = (const float*)d_in[3];
    const float* W2  = (const float*)d_in[4];
    const float* b2  = (const float*)d_in[5];
    const float* Wmu = (const float*)d_in[6];
    const float* bmu = (const float*)d_in[7];
    const float* Wlv = (const float*)d_in[8];
    const float* blv = (const float*)d_in[9];

    int N = in_sizes[0] / 32;
    int E = in_sizes[1] / 2;

    float* mu = (float*)d_out;
    float* lv = mu + (size_t)N * 32;

    float* bufA; float* bufB;
    cudaGetSymbolAddress((void**)&bufA, g_bufA);
    cudaGetSymbolAddress((void**)&bufB, g_bufB);

    const int T = 256;
    int gN = cdiv(N, T);                  // per-node
    int gE = cdiv(E, T);                  // per-edge
    int gW = cdiv((long long)N * 32, T);  // warp-per-node

    // CSR build
    k_detect<<<1, 512>>>((const int*)ei, E);
    k_zero_cnt<<<gN, T>>>(N);
    k_count<<<gE, T>>>(ei, E);
    k_rowalloc<<<gN, T>>>(N);
    k_permute<<<gE, T>>>(ei, E);

    // Layer 1: a1 = (A_hat x) W1 + b1
    k_layer<0><<<gW, T>>>(x, W1, b1, bufA, N);
    // Layer 2: a2 = (A_hat relu(a1)) W2 + b2
    k_layer<1><<<gW, T>>>(bufA, W2, b2, bufB, N);
    // Heads: g = A_hat relu(a2); mu = g Wmu + bmu; lv = g Wlv + blv
    k_layer2<<<gW, T>>>(bufB, Wmu, Wlv, bmu, blv, mu, lv, N);
}

// round 6
// speedup vs baseline: 1.0857x; 1.0857x over previous
#include <cuda_runtime.h>
#include <cuda_bf16.h>

// VGAE encoder, pull-based + aggregation/GEMM commutation:
//   A_hat (X W) = (A_hat X) W. Each layer = warp-per-node gather-aggregate over
//   CSR (float2 lane-split: 2 edges in flight per warp-iteration, unroll x4 ->
//   8 edges MLP) + in-register 32x32 GEMV via warp shuffles. mu/logvar heads
//   share one aggregation. 7 launches total.

#define N_MAX 131072
#define E_MAX 2097152

// Scratch (device globals; no allocations allowed)
__device__ int   g_is64;
__device__ int   g_alloc;            // CSR region allocator
__device__ int   g_cnt[N_MAX];       // in-degree (excluding self-loop)
__device__ int   g_rowstart[N_MAX];
__device__ int   g_cur[N_MAX];       // permutation cursor
__device__ float g_dis[N_MAX];       // deg^-1/2 (deg includes self-loop)
__device__ int2  g_adj[E_MAX];       // CSR payload: (src, __float_as_int(norm))
__device__ float g_bufA[(size_t)N_MAX * 32];
__device__ float g_bufB[(size_t)N_MAX * 32];

// ---------------------------------------------------------------------------
// Init: zero g_cnt (all blocks); block 0 also detects edge dtype.
// int64 indices (< N ~ 1e5) have all-zero odd int32 words; int32 data never
// has 256 consecutive zero odd words.
// ---------------------------------------------------------------------------

__global__ __launch_bounds__(256) void k_init(const int* __restrict__ ei32,
                                              int E, int n) {
    int i = blockIdx.x * blockDim.x + threadIdx.x;
    if (i < n) g_cnt[i] = 0;
    if (blockIdx.x == 0) {
        int t = threadIdx.x;
        int n_check = 256 < E ? 256 : E;
        int nz = (t < n_check && ei32[2 * t + 1] != 0) ? 1 : 0;
        int any = __syncthreads_or(nz);
        if (t == 0) {
            g_is64 = !any;
            g_alloc = 0;
        }
    }
}

// Count in-degrees, 4 edges per thread (vectorized loads).
__global__ __launch_bounds__(256) void k_count(const void* __restrict__ eiv, int E) {
    int t = blockIdx.x * blockDim.x + threadIdx.x;
    int e0 = t * 4;
    if (e0 >= E) return;
    int d[4];
    int m = (E - e0 < 4) ? (E - e0) : 4;
    if (g_is64) {
        const long long* ei = (const long long*)eiv + (size_t)E + e0;
        if (m == 4) {
            longlong2 a = ((const longlong2*)ei)[0];
            longlong2 b = ((const longlong2*)ei)[1];
            d[0] = (int)a.x; d[1] = (int)a.y; d[2] = (int)b.x; d[3] = (int)b.y;
        } else {
            for (int k = 0; k < m; k++) d[k] = (int)ei[k];
        }
    } else {
        const int* ei = (const int*)eiv + (size_t)E + e0;
        if (m == 4) {
            int4 a = *(const int4*)ei;
            d[0] = a.x; d[1] = a.y; d[2] = a.z; d[3] = a.w;
        } else {
            for (int k = 0; k < m; k++) d[k] = ei[k];
        }
    }
    for (int k = 0; k < m; k++) atomicAdd(&g_cnt[d[k]], 1);
}

// Atomic CSR region allocation: each node grabs a contiguous [rs, rs+cnt)
// slice of g_adj. Segment ordering across nodes is arbitrary — irrelevant
// for the warp-per-node gather, which streams its own segment.
__global__ void k_rowalloc(int n) {
    int i = blockIdx.x * blockDim.x + threadIdx.x;
    if (i >= n) return;
    int c = g_cnt[i];
    int rs = atomicAdd(&g_alloc, c);
    g_rowstart[i] = rs;
    g_cur[i] = rs;
    g_dis[i] = rsqrtf((float)(c + 1));  // +1 self-loop
}

__global__ void k_permute(const void* __restrict__ eiv, int E) {
    int e = blockIdx.x * blockDim.x + threadIdx.x;
    if (e >= E) return;
    int s, d;
    if (g_is64) {
        const long long* ei = (const long long*)eiv;
        s = (int)ei[e];
        d = (int)ei[(size_t)E + e];
    } else {
        const int* ei = (const int*)eiv;
        s = ei[e];
        d = ei[(size_t)E + e];
    }
    int pos = atomicAdd(&g_cur[d], 1);
    int2 ev;
    ev.x = s;
    ev.y = __float_as_int(g_dis[s] * g_dis[d]);
    g_adj[pos] = ev;
}

// ---------------------------------------------------------------------------
// Fused layer, float2 lane-split: warp = node; half-warps process alternating
// edges; lane holds channels (2*sub, 2*sub+1) as float2.
//   t = dis^2 * r(h[i]) + sum_j norm_j * r(h[src_j]);   out = t @ W + b
// ---------------------------------------------------------------------------

__device__ __forceinline__ float2 relu2(float2 v) {
    v.x = fmaxf(v.x, 0.0f); v.y = fmaxf(v.y, 0.0f); return v;
}

template <int RELU>
__global__ __launch_bounds__(256) void k_layer(
    const float* __restrict__ h, const float* __restrict__ W,
    const float* __restrict__ b, float* __restrict__ out, int n)
{
    __shared__ float sW[1024];  // W[k][j] at sW[k*32+j]
    ((float4*)sW)[threadIdx.x] = ((const float4*)W)[threadIdx.x];
    __syncthreads();

    int warp = (blockIdx.x * blockDim.x + threadIdx.x) >> 5;
    int lane = threadIdx.x & 31;
    if (warp >= n) return;

    int half = lane >> 4;      // 0 or 1
    int sub  = lane & 15;      // channel pair index
    const float2* h2 = (const float2*)h;

    int rs  = g_rowstart[warp];
    int cnt = g_cnt[warp];
    float dis = g_dis[warp];

    // self term (half 0 only; halves are summed later)
    float2 acc = make_float2(0.0f, 0.0f);
    if (half == 0) {
        float2 sv = h2[(size_t)warp * 16 + sub];
        if (RELU) sv = relu2(sv);
        acc.x = dis * dis * sv.x;
        acc.y = dis * dis * sv.y;
    }

    int j = rs, end = rs + cnt;
    // 8 edges per iteration (4 per half-warp)
    for (; j + 8 <= end; j += 8) {
        int2 e0 = g_adj[j + 0 + half];
        int2 e1 = g_adj[j + 2 + half];
        int2 e2 = g_adj[j + 4 + half];
        int2 e3 = g_adj[j + 6 + half];
        float2 v0 = h2[(size_t)e0.x * 16 + sub];
        float2 v1 = h2[(size_t)e1.x * 16 + sub];
        float2 v2 = h2[(size_t)e2.x * 16 + sub];
        float2 v3 = h2[(size_t)e3.x * 16 + sub];
        if (RELU) { v0 = relu2(v0); v1 = relu2(v1); v2 = relu2(v2); v3 = relu2(v3); }
        float w0 = __int_as_float(e0.y);
        float w1 = __int_as_float(e1.y);
        float w2 = __int_as_float(e2.y);
        float w3 = __int_as_float(e3.y);
        acc.x += w0 * v0.x + w1 * v1.x + w2 * v2.x + w3 * v3.x;
        acc.y += w0 * v0.y + w1 * v1.y + w2 * v2.y + w3 * v3.y;
    }
    for (; j + 2 <= end; j += 2) {
        int2 e = g_adj[j + half];
        float2 v = h2[(size_t)e.x * 16 + sub];
        if (RELU) v = relu2(v);
        float w = __int_as_float(e.y);
        acc.x += w * v.x;
        acc.y += w * v.y;
    }
    if (j < end && half == 0) {  // odd leftover: half 0 takes it
        int2 e = g_adj[j];
        float2 v = h2[(size_t)e.x * 16 + sub];
        if (RELU) v = relu2(v);
        float w = __int_as_float(e.y);
        acc.x += w * v.x;
        acc.y += w * v.y;
    }

    // combine halves: all lanes now hold t[2*sub], t[2*sub+1]
    acc.x += __shfl_xor_sync(0xFFFFFFFFu, acc.x, 16);
    acc.y += __shfl_xor_sync(0xFFFFFFFFu, acc.y, 16);

    // GEMV: out[lane] = b[lane] + sum_k t[k] * W[k][lane]
    float o = b[lane];
#pragma unroll
    for (int m = 0; m < 16; m++) {
        float t0 = __shfl_sync(0xFFFFFFFFu, acc.x, m);
        float t1 = __shfl_sync(0xFFFFFFFFu, acc.y, m);
        o += t0 * sW[(2 * m) * 32 + lane] + t1 * sW[(2 * m + 1) * 32 + lane];
    }
    out[(size_t)warp * 32 + lane] = o;
}

// Fused dual head: one aggregation, two GEMVs (mu and logvar).
__global__ __launch_bounds__(256) void k_layer2(
    const float* __restrict__ h,
    const float* __restrict__ Wa, const float* __restrict__ Wb,
    const float* __restrict__ ba, const float* __restrict__ bb,
    float* __restrict__ oa, float* __restrict__ ob, int n)
{
    __shared__ float sWa[1024];
    __shared__ float sWb[1024];
    ((float4*)sWa)[threadIdx.x] = ((const float4*)Wa)[threadIdx.x];
    ((float4*)sWb)[threadIdx.x] = ((const float4*)Wb)[threadIdx.x];
    __syncthreads();

    int warp = (blockIdx.x * blockDim.x + threadIdx.x) >> 5;
    int lane = threadIdx.x & 31;
    if (warp >= n) return;

    int half = lane >> 4;
    int sub  = lane & 15;
    const float2* h2 = (const float2*)h;

    int rs  = g_rowstart[warp];
    int cnt = g_cnt[warp];
    float dis = g_dis[warp];

    float2 acc = make_float2(0.0f, 0.0f);
    if (half == 0) {
        float2 sv = relu2(h2[(size_t)warp * 16 + sub]);
        acc.x = dis * dis * sv.x;
        acc.y = dis * dis * sv.y;
    }

    int j = rs, end = rs + cnt;
    for (; j + 8 <= end; j += 8) {
        int2 e0 = g_adj[j + 0 + half];
        int2 e1 = g_adj[j + 2 + half];
        int2 e2 = g_adj[j + 4 + half];
        int2 e3 = g_adj[j + 6 + half];
        float2 v0 = relu2(h2[(size_t)e0.x * 16 + sub]);
        float2 v1 = relu2(h2[(size_t)e1.x * 16 + sub]);
        float2 v2 = relu2(h2[(size_t)e2.x * 16 + sub]);
        float2 v3 = relu2(h2[(size_t)e3.x * 16 + sub]);
        float w0 = __int_as_float(e0.y);
        float w1 = __int_as_float(e1.y);
        float w2 = __int_as_float(e2.y);
        float w3 = __int_as_float(e3.y);
        acc.x += w0 * v0.x + w1 * v1.x + w2 * v2.x + w3 * v3.x;
        acc.y += w0 * v0.y + w1 * v1.y + w2 * v2.y + w3 * v3.y;
    }
    for (; j + 2 <= end; j += 2) {
        int2 e = g_adj[j + half];
        float2 v = relu2(h2[(size_t)e.x * 16 + sub]);
        float w = __int_as_float(e.y);
        acc.x += w * v.x;
        acc.y += w * v.y;
    }
    if (j < end && half == 0) {
        int2 e = g_adj[j];
        float2 v = relu2(h2[(size_t)e.x * 16 + sub]);
        float w = __int_as_float(e.y);
        acc.x += w * v.x;
        acc.y += w * v.y;
    }

    acc.x += __shfl_xor_sync(0xFFFFFFFFu, acc.x, 16);
    acc.y += __shfl_xor_sync(0xFFFFFFFFu, acc.y, 16);

    float omu = ba[lane];
    float olv = bb[lane];
#pragma unroll
    for (int m = 0; m < 16; m++) {
        float t0 = __shfl_sync(0xFFFFFFFFu, acc.x, m);
        float t1 = __shfl_sync(0xFFFFFFFFu, acc.y, m);
        omu += t0 * sWa[(2 * m) * 32 + lane] + t1 * sWa[(2 * m + 1) * 32 + lane];
        olv += t0 * sWb[(2 * m) * 32 + lane] + t1 * sWb[(2 * m + 1) * 32 + lane];
    }
    size_t self = (size_t)warp * 32 + lane;
    oa[self] = omu;
    ob[self] = olv;
}

// ---------------------------------------------------------------------------
// Launch
// ---------------------------------------------------------------------------

static inline int cdiv(long long a, int b) { return (int)((a + b - 1) / b); }

extern "C" void kernel_launch(void* const* d_in, const int* in_sizes, int n_in,
                              void* d_out, int out_size)
{
    const float* x   = (const float*)d_in[0];
    const void*  ei  = d_in[1];
    const float* W1  = (const float*)d_in[2];
    const float* b1  = (const float*)d_in[3];
    const float* W2  = (const float*)d_in[4];
    const float* b2  = (const float*)d_in[5];
    const float* Wmu = (const float*)d_in[6];
    const float* bmu = (const float*)d_in[7];
    const float* Wlv = (const float*)d_in[8];
    const float* blv = (const float*)d_in[9];

    int N = in_sizes[0] / 32;
    int E = in_sizes[1] / 2;

    float* mu = (float*)d_out;
    float* lv = mu + (size_t)N * 32;

    float* bufA; float* bufB;
    cudaGetSymbolAddress((void**)&bufA, g_bufA);
    cudaGetSymbolAddress((void**)&bufB, g_bufB);

    const int T = 256;
    int gN  = cdiv(N, T);                  // per-node
    int gE  = cdiv(E, T);                  // per-edge
    int gE4 = cdiv(E, T * 4);              // 4 edges per thread
    int gW  = cdiv((long long)N * 32, T);  // warp-per-node

    // CSR build
    k_init<<<gN, T>>>((const int*)ei, E, N);
    k_count<<<gE4, T>>>(ei, E);
    k_rowalloc<<<gN, T>>>(N);
    k_permute<<<gE, T>>>(ei, E);

    // Layer 1: a1 = (A_hat x) W1 + b1
    k_layer<0><<<gW, T>>>(x, W1, b1, bufA, N);
    // Layer 2: a2 = (A_hat relu(a1)) W2 + b2
    k_layer<1><<<gW, T>>>(bufA, W2, b2, bufB, N);
    // Heads: g = A_hat relu(a2); mu = g Wmu + bmu; lv = g Wlv + blv
    k_layer2<<<gW, T>>>(bufB, Wmu, Wlv, bmu, blv, mu, lv, N);
}

// round 7
// speedup vs baseline: 1.1071x; 1.0197x over previous
#include <cuda_runtime.h>
#include <cuda_bf16.h>

// VGAE encoder, pull-based, rank-1 norm factored out:
//   norm_ij = dis_i*dis_j  =>  out_i = dis_i * (u_i + sum_{j in N(i)} u_j),  u = dis (.) h.
// Each layer stores its output pre-scaled by dis (relu commutes with dis>0), so the
// CSR payload is src-only (int), and the gather loop has no per-edge weights.
// Layer = warp-per-node gather (float2 lane-split, int4 adj loads) + shuffle GEMV.

#define N_MAX 131072
#define E_MAX 2097152   // >= E + 3*N (per-node padding to 4)

// Scratch (device globals; no allocations allowed)
__device__ int   g_is64;
__device__ int   g_alloc;            // CSR region allocator
__device__ int   g_cnt[N_MAX];       // in-degree (excluding self-loop)
__device__ int   g_rowstart[N_MAX];
__device__ int   g_cur[N_MAX];       // permutation cursor
__device__ float g_dis[N_MAX];       // deg^-1/2 (deg includes self-loop)
__device__ int   g_adjs[E_MAX];      // CSR payload: src only
__device__ float g_bufA[(size_t)N_MAX * 32];
__device__ float g_bufB[(size_t)N_MAX * 32];

// ---------------------------------------------------------------------------
// Init: zero g_cnt (all blocks); block 0 also detects edge dtype.
// int64 indices (< N ~ 1e5) have all-zero odd int32 words; int32 data never
// has 256 consecutive zero odd words.
// ---------------------------------------------------------------------------

__global__ __launch_bounds__(256) void k_init(const int* __restrict__ ei32,
                                              int E, int n) {
    int i = blockIdx.x * blockDim.x + threadIdx.x;
    if (i < n) g_cnt[i] = 0;
    if (blockIdx.x == 0) {
        int t = threadIdx.x;
        int n_check = 256 < E ? 256 : E;
        int nz = (t < n_check && ei32[2 * t + 1] != 0) ? 1 : 0;
        int any = __syncthreads_or(nz);
        if (t == 0) {
            g_is64 = !any;
            g_alloc = 0;
        }
    }
}

// Count in-degrees, 4 edges per thread (vectorized loads).
__global__ __launch_bounds__(256) void k_count(const void* __restrict__ eiv, int E) {
    int t = blockIdx.x * blockDim.x + threadIdx.x;
    int e0 = t * 4;
    if (e0 >= E) return;
    int d[4];
    int m = (E - e0 < 4) ? (E - e0) : 4;
    if (g_is64) {
        const long long* ei = (const long long*)eiv + (size_t)E + e0;
        if (m == 4) {
            longlong2 a = ((const longlong2*)ei)[0];
            longlong2 b = ((const longlong2*)ei)[1];
            d[0] = (int)a.x; d[1] = (int)a.y; d[2] = (int)b.x; d[3] = (int)b.y;
        } else {
            for (int k = 0; k < m; k++) d[k] = (int)ei[k];
        }
    } else {
        const int* ei = (const int*)eiv + (size_t)E + e0;
        if (m == 4) {
            int4 a = *(const int4*)ei;
            d[0] = a.x; d[1] = a.y; d[2] = a.z; d[3] = a.w;
        } else {
            for (int k = 0; k < m; k++) d[k] = ei[k];
        }
    }
    for (int k = 0; k < m; k++) atomicAdd(&g_cnt[d[k]], 1);
}

// Atomic CSR region allocation, padded to 4 entries for int4-aligned loads.
__global__ void k_rowalloc(int n) {
    int i = blockIdx.x * blockDim.x + threadIdx.x;
    if (i >= n) return;
    int c = g_cnt[i];
    int rs = atomicAdd(&g_alloc, (c + 3) & ~3);
    g_rowstart[i] = rs;
    g_cur[i] = rs;
    g_dis[i] = rsqrtf((float)(c + 1));  // +1 self-loop
}

__global__ void k_permute(const void* __restrict__ eiv, int E) {
    int e = blockIdx.x * blockDim.x + threadIdx.x;
    if (e >= E) return;
    int s, d;
    if (g_is64) {
        const long long* ei = (const long long*)eiv;
        s = (int)ei[e];
        d = (int)ei[(size_t)E + e];
    } else {
        const int* ei = (const int*)eiv;
        s = ei[e];
        d = ei[(size_t)E + e];
    }
    int pos = atomicAdd(&g_cur[d], 1);
    g_adjs[pos] = s;
}

// u = dis (.) x  (layer-1 input pre-scale)
__global__ __launch_bounds__(256) void k_prescale(const float* __restrict__ x,
                                                  float* __restrict__ u, int n) {
    int i = blockIdx.x * blockDim.x + threadIdx.x;
    if (i >= n * 16) return;
    float s = g_dis[i >> 4];
    float2 v = ((const float2*)x)[i];
    v.x *= s; v.y *= s;
    ((float2*)u)[i] = v;
}

// ---------------------------------------------------------------------------
// Fused layer: warp = node; half-warps take alternating 4-edge int4 chunks;
// lane holds channels (2*sub, 2*sub+1) as float2.
//   t = r(u_i) + sum_j r(u_src_j);  o = b + dis_i * (t @ W);  out = PRE ? dis_i*o : o
// r() = relu if RELU (u stores pre-scaled activations; relu commutes with dis>0).
// ---------------------------------------------------------------------------

__device__ __forceinline__ float2 relu2(float2 v) {
    v.x = fmaxf(v.x, 0.0f); v.y = fmaxf(v.y, 0.0f); return v;
}

template <int RELU, int PRE_OUT>
__global__ __launch_bounds__(256) void k_layer(
    const float* __restrict__ u, const float* __restrict__ W,
    const float* __restrict__ b, float* __restrict__ out, int n)
{
    __shared__ float sW[1024];  // W[k][j] at sW[k*32+j]
    ((float4*)sW)[threadIdx.x] = ((const float4*)W)[threadIdx.x];
    __syncthreads();

    int warp = (blockIdx.x * blockDim.x + threadIdx.x) >> 5;
    int lane = threadIdx.x & 31;
    if (warp >= n) return;

    int half = lane >> 4;      // 0 or 1
    int sub  = lane & 15;      // channel pair index
    const float2* u2 = (const float2*)u;

    int rs  = g_rowstart[warp];
    int cnt = g_cnt[warp];
    float dis = g_dis[warp];

    // self term (half 0 only; halves summed later)
    float2 acc = make_float2(0.0f, 0.0f);
    if (half == 0) {
        float2 sv = u2[(size_t)warp * 16 + sub];
        if (RELU) sv = relu2(sv);
        acc = sv;
    }

    int j = rs, end = rs + cnt;
    // 8 edges per iteration: each half-warp loads one int4 (4 src indices)
    for (; j + 8 <= end; j += 8) {
        int4 e = *(const int4*)(g_adjs + j + 4 * half);
        float2 v0 = u2[(size_t)e.x * 16 + sub];
        float2 v1 = u2[(size_t)e.y * 16 + sub];
        float2 v2 = u2[(size_t)e.z * 16 + sub];
        float2 v3 = u2[(size_t)e.w * 16 + sub];
        if (RELU) { v0 = relu2(v0); v1 = relu2(v1); v2 = relu2(v2); v3 = relu2(v3); }
        acc.x += (v0.x + v1.x) + (v2.x + v3.x);
        acc.y += (v0.y + v1.y) + (v2.y + v3.y);
    }
    for (; j + 2 <= end; j += 2) {
        int s = g_adjs[j + half];
        float2 v = u2[(size_t)s * 16 + sub];
        if (RELU) v = relu2(v);
        acc.x += v.x; acc.y += v.y;
    }
    if (j < end && half == 0) {
        int s = g_adjs[j];
        float2 v = u2[(size_t)s * 16 + sub];
        if (RELU) v = relu2(v);
        acc.x += v.x; acc.y += v.y;
    }

    // combine halves: lanes hold t[2*sub], t[2*sub+1]
    acc.x += __shfl_xor_sync(0xFFFFFFFFu, acc.x, 16);
    acc.y += __shfl_xor_sync(0xFFFFFFFFu, acc.y, 16);

    // GEMV: o = b[lane] + dis * sum_k t[k]*W[k][lane]
    float s = 0.0f;
#pragma unroll
    for (int m = 0; m < 16; m++) {
        float t0 = __shfl_sync(0xFFFFFFFFu, acc.x, m);
        float t1 = __shfl_sync(0xFFFFFFFFu, acc.y, m);
        s += t0 * sW[(2 * m) * 32 + lane] + t1 * sW[(2 * m + 1) * 32 + lane];
    }
    float o = b[lane] + dis * s;
    if (PRE_OUT) o *= dis;  // store pre-scaled for next layer's gather
    out[(size_t)warp * 32 + lane] = o;
}

// Fused dual head: one aggregation, two GEMVs (mu and logvar), unscaled outputs.
__global__ __launch_bounds__(256) void k_layer2(
    const float* __restrict__ u,
    const float* __restrict__ Wa, const float* __restrict__ Wb,
    const float* __restrict__ ba, const float* __restrict__ bb,
    float* __restrict__ oa, float* __restrict__ ob, int n)
{
    __shared__ float sWa[1024];
    __shared__ float sWb[1024];
    ((float4*)sWa)[threadIdx.x] = ((const float4*)Wa)[threadIdx.x];
    ((float4*)sWb)[threadIdx.x] = ((const float4*)Wb)[threadIdx.x];
    __syncthreads();

    int warp = (blockIdx.x * blockDim.x + threadIdx.x) >> 5;
    int lane = threadIdx.x & 31;
    if (warp >= n) return;

    int half = lane >> 4;
    int sub  = lane & 15;
    const float2* u2 = (const float2*)u;

    int rs  = g_rowstart[warp];
    int cnt = g_cnt[warp];
    float dis = g_dis[warp];

    float2 acc = make_float2(0.0f, 0.0f);
    if (half == 0) acc = relu2(u2[(size_t)warp * 16 + sub]);

    int j = rs, end = rs + cnt;
    for (; j + 8 <= end; j += 8) {
        int4 e = *(const int4*)(g_adjs + j + 4 * half);
        float2 v0 = relu2(u2[(size_t)e.x * 16 + sub]);
        float2 v1 = relu2(u2[(size_t)e.y * 16 + sub]);
        float2 v2 = relu2(u2[(size_t)e.z * 16 + sub]);
        float2 v3 = relu2(u2[(size_t)e.w * 16 + sub]);
        acc.x += (v0.x + v1.x) + (v2.x + v3.x);
        acc.y += (v0.y + v1.y) + (v2.y + v3.y);
    }
    for (; j + 2 <= end; j += 2) {
        float2 v = relu2(u2[(size_t)g_adjs[j + half] * 16 + sub]);
        acc.x += v.x; acc.y += v.y;
    }
    if (j < end && half == 0) {
        float2 v = relu2(u2[(size_t)g_adjs[j] * 16 + sub]);
        acc.x += v.x; acc.y += v.y;
    }

    acc.x += __shfl_xor_sync(0xFFFFFFFFu, acc.x, 16);
    acc.y += __shfl_xor_sync(0xFFFFFFFFu, acc.y, 16);

    float sa = 0.0f, sb = 0.0f;
#pragma unroll
    for (int m = 0; m < 16; m++) {
        float t0 = __shfl_sync(0xFFFFFFFFu, acc.x, m);
        float t1 = __shfl_sync(0xFFFFFFFFu, acc.y, m);
        sa += t0 * sWa[(2 * m) * 32 + lane] + t1 * sWa[(2 * m + 1) * 32 + lane];
        sb += t0 * sWb[(2 * m) * 32 + lane] + t1 * sWb[(2 * m + 1) * 32 + lane];
    }
    size_t self = (size_t)warp * 32 + lane;
    oa[self] = ba[lane] + dis * sa;
    ob[self] = bb[lane] + dis * sb;
}

// ---------------------------------------------------------------------------
// Launch
// ---------------------------------------------------------------------------

static inline int cdiv(long long a, int b) { return (int)((a + b - 1) / b); }

extern "C" void kernel_launch(void* const* d_in, const int* in_sizes, int n_in,
                              void* d_out, int out_size)
{
    const float* x   = (const float*)d_in[0];
    const void*  ei  = d_in[1];
    const float* W1  = (const float*)d_in[2];
    const float* b1  = (const float*)d_in[3];
    const float* W2  = (const float*)d_in[4];
    const float* b2  = (const float*)d_in[5];
    const float* Wmu = (const float*)d_in[6];
    const float* bmu = (const float*)d_in[7];
    const float* Wlv = (const float*)d_in[8];
    const float* blv = (const float*)d_in[9];

    int N = in_sizes[0] / 32;
    int E = in_sizes[1] / 2;

    float* mu = (float*)d_out;
    float* lv = mu + (size_t)N * 32;

    float* bufA; float* bufB;
    cudaGetSymbolAddress((void**)&bufA, g_bufA);
    cudaGetSymbolAddress((void**)&bufB, g_bufB);

    const int T = 256;
    int gN  = cdiv(N, T);                  // per-node
    int gE  = cdiv(E, T);                  // per-edge
    int gE4 = cdiv(E, T * 4);              // 4 edges per thread
    int gP  = cdiv((long long)N * 16, T);  // per-float2
    int gW  = cdiv((long long)N * 32, T);  // warp-per-node

    // CSR build (src-only payload) + layer-1 pre-scale
    k_init<<<gN, T>>>((const int*)ei, E, N);
    k_count<<<gE4, T>>>(ei, E);
    k_rowalloc<<<gN, T>>>(N);
    k_prescale<<<gP, T>>>(x, bufA, N);
    k_permute<<<gE, T>>>(ei, E);

    // Layer 1: a1 = (A_hat x) W1 + b1, stored as dis (.) a1
    k_layer<0, 1><<<gW, T>>>(bufA, W1, b1, bufB, N);
    // Layer 2: a2 = (A_hat relu(a1)) W2 + b2, stored as dis (.) a2
    k_layer<1, 1><<<gW, T>>>(bufB, W2, b2, bufA, N);
    // Heads: g = A_hat relu(a2); mu = g Wmu + bmu; lv = g Wlv + blv
    k_layer2<<<gW, T>>>(bufA, Wmu, Wlv, bmu, blv, mu, lv, N);
}